// round 9
// baseline (speedup 1.0000x reference)
#include <cuda_runtime.h>
#include <cstdint>

#define N_DIM 4096
#define NELEM (N_DIM * N_DIM)

// ---------------- device scratch ----------------
__device__ unsigned g_amax_bits[2];
__device__ signed char g_qa[NELEM];          // quantized lhs, [M][K]
__device__ signed char g_qb[NELEM];          // quantized rhs^T, [N][K]

// ---------------- helpers ----------------
__device__ __forceinline__ uint32_t smem_u32(const void* p) {
    uint32_t a;
    asm("{ .reg .u64 t; cvta.to.shared.u64 t, %1; cvt.u32.u64 %0, t; }" : "=r"(a) : "l"(p));
    return a;
}
__device__ __forceinline__ void cp16s(uint32_t smem, const void* gmem) {
    asm volatile("cp.async.cg.shared.global [%0], [%1], 16;\n" :: "r"(smem), "l"(gmem));
}
__device__ __forceinline__ void cp_commit() { asm volatile("cp.async.commit_group;\n"); }
template <int N> __device__ __forceinline__ void cp_wait() {
    asm volatile("cp.async.wait_group %0;\n" :: "n"(N));
}
__device__ __forceinline__ void ldsm_x4(uint32_t& r0, uint32_t& r1, uint32_t& r2,
                                        uint32_t& r3, uint32_t addr) {
    asm volatile("ldmatrix.sync.aligned.m8n8.x4.shared.b16 {%0,%1,%2,%3}, [%4];"
                 : "=r"(r0), "=r"(r1), "=r"(r2), "=r"(r3) : "r"(addr));
}
__device__ __forceinline__ signed char quant1(float v, float s) {
    float q = rintf(v * s);
    q = fminf(fmaxf(q, -127.0f), 127.0f);
    return (signed char)(int)q;
}

// ---------------- launch #1: reset ----------------
__global__ void reset_kernel() {
    g_amax_bits[0] = 0u;
    g_amax_bits[1] = 0u;
}

// ---------------- launch #2: abs-max for BOTH tensors ----------------
__global__ void amax_both_kernel(const float* __restrict__ lhs,
                                 const float* __restrict__ rhs) {
    const int half = gridDim.x >> 1;
    const int sel = (blockIdx.x >= half) ? 1 : 0;
    const float* x = sel ? rhs : lhs;
    const int bid = sel ? (blockIdx.x - half) : blockIdx.x;

    int tid = bid * blockDim.x + threadIdx.x;
    int stride = half * blockDim.x;
    const float4* x4 = (const float4*)x;
    float m = 0.0f;
    for (int i = tid; i < NELEM / 4; i += stride) {
        float4 v = x4[i];
        m = fmaxf(m, fmaxf(fmaxf(fabsf(v.x), fabsf(v.y)),
                           fmaxf(fabsf(v.z), fabsf(v.w))));
    }
    #pragma unroll
    for (int o = 16; o; o >>= 1) m = fmaxf(m, __shfl_xor_sync(0xffffffffu, m, o));
    __shared__ float sm[32];
    int lane = threadIdx.x & 31, w = threadIdx.x >> 5;
    if (lane == 0) sm[w] = m;
    __syncthreads();
    if (w == 0) {
        m = (lane < (int)(blockDim.x >> 5)) ? sm[lane] : 0.0f;
        #pragma unroll
        for (int o = 16; o; o >>= 1) m = fmaxf(m, __shfl_xor_sync(0xffffffffu, m, o));
        if (lane == 0) atomicMax(&g_amax_bits[sel], __float_as_uint(m));
    }
}

// ---------------- launch #3: quantize lhs + quantize/transpose rhs ----------------
// grid (128, 128, 2), block (32, 8)
__global__ void quant_both_kernel(const float* __restrict__ lhs,
                                  const float* __restrict__ rhs) {
    const int tid256 = threadIdx.y * 32 + threadIdx.x;
    if (blockIdx.z == 0) {
        float amax = fmaxf(__uint_as_float(g_amax_bits[0]), 1e-12f);
        float s = 127.0f / amax;
        const int bid = blockIdx.y * gridDim.x + blockIdx.x;
        const int i = bid * 256 + tid256;
        float4 v = ((const float4*)lhs)[i];
        char4 q;
        q.x = quant1(v.x, s); q.y = quant1(v.y, s);
        q.z = quant1(v.z, s); q.w = quant1(v.w, s);
        ((char4*)g_qa)[i] = q;
    } else {
        __shared__ signed char tile[32][36];
        float amax = fmaxf(__uint_as_float(g_amax_bits[1]), 1e-12f);
        float s = 127.0f / amax;
        const int k0 = blockIdx.y * 32;
        const int n0 = blockIdx.x * 32;
        const int tx = threadIdx.x, ty = threadIdx.y;
        #pragma unroll
        for (int i = 0; i < 4; i++) {
            int k = ty + i * 8;
            float v = rhs[(size_t)(k0 + k) * N_DIM + n0 + tx];
            tile[tx][k] = quant1(v, s);
        }
        __syncthreads();
        #pragma unroll
        for (int i = 0; i < 4; i++) {
            int n = ty + i * 8;
            g_qb[(size_t)(n0 + n) * N_DIM + k0 + tx] = tile[n][tx];
        }
    }
}

// ---------------- launch #4: hybrid s8 GEMM, fine-grained interleave ----------------
// 128x128x128 tile, 3-stage cp.async.  Per K-tile of 128:
//   k[0,64)   -> mma.m16n8k32 (tensor pipe)  into acc
//   k[64,128) -> __dp4a        (integer pipe) into acc2 (independent regs)
// Emitted as 32 x { 1 mma ; 32 dp4a } so both pipes run concurrently.
#define BM 128
#define BN 128
#define BKB 128
#define STAGES 3
#define NKT (N_DIM / BKB)                     // 32
#define A_STAGE_BYTES (BM * BKB)              // 16384
#define B_STAGE_BYTES (BN * BKB)              // 16384
#define STAGE_BYTES (A_STAGE_BYTES + B_STAGE_BYTES)   // 32768
#define GEMM_SMEM (STAGES * STAGE_BYTES)      // 98304

__global__ __launch_bounds__(256, 1) void gemm_s8_hybrid2(float* __restrict__ out) {
    extern __shared__ __align__(1024) char smem[];
    const uint32_t smem_base = smem_u32(smem);
    const int tid = threadIdx.x;
    const int wid = tid >> 5, lane = tid & 31;
    const int wm = wid & 3;           // 0..3 : 32-row band of M
    const int wn = wid >> 2;          // 0..1 : 64-col band of N
    const int bm = blockIdx.y, bn = blockIdx.x;

    int acc[2][8][4];                 // tensor accumulators
    int acc2[2][8][4];                // dp4a accumulators (independent)
    #pragma unroll
    for (int a = 0; a < 2; a++)
        #pragma unroll
        for (int b = 0; b < 8; b++)
            #pragma unroll
            for (int c = 0; c < 4; c++) { acc[a][b][c] = 0; acc2[a][b][c] = 0; }

    const signed char* gA = g_qa + (size_t)(bm * BM) * N_DIM;
    const signed char* gB = g_qb + (size_t)(bn * BN) * N_DIM;

    auto load_stage = [&](int s, int kt) {
        const uint32_t sa = smem_base + s * STAGE_BYTES;
        const uint32_t sb = sa + A_STAGE_BYTES;
        #pragma unroll
        for (int i = 0; i < 4; i++) {
            const int ci = tid + i * 256;
            const int row = ci >> 3, c = ci & 7;
            cp16s(sa + row * 128 + ((c ^ (row & 7)) << 4),
                  gA + (size_t)row * N_DIM + kt * BKB + c * 16);
        }
        #pragma unroll
        for (int i = 0; i < 4; i++) {
            const int ci = tid + i * 256;
            const int row = ci >> 3, c = ci & 7;
            cp16s(sb + row * 128 + ((c ^ (row & 7)) << 4),
                  gB + (size_t)row * N_DIM + kt * BKB + c * 16);
        }
        cp_commit();
    };

    #pragma unroll
    for (int s = 0; s < STAGES; s++) load_stage(s, s);

    const int lrow16 = lane & 15;
    const int half = (lane >> 4) & 1;
    const int swz = lane & 7;
    const int group = lane >> 2, tig = lane & 3;

    for (int kt = 0; kt < NKT; kt++) {
        const int buf = kt % STAGES;
        {
            const int rem = NKT - kt;
            if (rem > 2) cp_wait<2>();
            else if (rem == 2) cp_wait<1>();
            else cp_wait<0>();
        }
        __syncthreads();

        const uint32_t sa = smem_base + buf * STAGE_BYTES;
        const uint32_t sb = sa + A_STAGE_BYTES;
        const char* sAp = smem + buf * STAGE_BYTES;
        const char* sBp = sAp + A_STAGE_BYTES;
        const uint32_t aRowBase = sa + (wm * 32 + lrow16) * 128;
        const uint32_t bRowBase = sb + (wn * 64 + lrow16) * 128;
        const int r0 = wm * 32 + group;
        const int cb0 = wn * 64 + tig * 2;
        const int xb0s = tig * 2, xb1s = tig * 2 + 1;

        #pragma unroll
        for (int ks = 0; ks < 2; ks++) {
            // tensor fragments for k-chunks [2ks, 2ks+1]
            const uint32_t cs = (uint32_t)(((ks * 2 + half) ^ swz) << 4);
            uint32_t af[2][4];
            #pragma unroll
            for (int mf = 0; mf < 2; mf++)
                ldsm_x4(af[mf][0], af[mf][1], af[mf][2], af[mf][3],
                        aRowBase + mf * 16 * 128 + cs);
            uint32_t bf[8][2];
            #pragma unroll
            for (int np = 0; np < 4; np++) {
                uint32_t m0, m1, m2, m3;
                ldsm_x4(m0, m1, m2, m3, bRowBase + np * 16 * 128 + cs);
                bf[2 * np][0] = m0; bf[2 * np + 1][0] = m1;
                bf[2 * np][1] = m2; bf[2 * np + 1][1] = m3;
            }

            #pragma unroll
            for (int hc = 0; hc < 2; hc++) {
                const int c = 4 + ks * 2 + hc;    // dp4a k-chunk (4..7)
                const int mf = hc;                // mma mf row-block this half
                const int xa = (c ^ group) << 4;
                const int4 A0 = *(const int4*)(sAp + (r0     ) * 128 + xa);
                const int4 A1 = *(const int4*)(sAp + (r0 +  8) * 128 + xa);
                const int4 A2 = *(const int4*)(sAp + (r0 + 16) * 128 + xa);
                const int4 A3 = *(const int4*)(sAp + (r0 + 24) * 128 + xa);
                const int Aw[4][4] = {{A0.x, A0.y, A0.z, A0.w},
                                      {A1.x, A1.y, A1.z, A1.w},
                                      {A2.x, A2.y, A2.z, A2.w},
                                      {A3.x, A3.y, A3.z, A3.w}};
                const int xb0 = (c ^ xb0s) << 4;
                const int xb1 = (c ^ xb1s) << 4;

                #pragma unroll
                for (int nf = 0; nf < 8; nf++) {
                    // ---- 1 tensor mma (async pipe, independent acc) ----
                    asm volatile(
                        "mma.sync.aligned.m16n8k32.row.col.s32.s8.s8.s32 "
                        "{%0,%1,%2,%3}, {%4,%5,%6,%7}, {%8,%9}, {%0,%1,%2,%3};\n"
                        : "+r"(acc[mf][nf][0]), "+r"(acc[mf][nf][1]),
                          "+r"(acc[mf][nf][2]), "+r"(acc[mf][nf][3])
                        : "r"(af[mf][0]), "r"(af[mf][1]), "r"(af[mf][2]), "r"(af[mf][3]),
                          "r"(bf[nf][0]), "r"(bf[nf][1]));

                    // ---- 32 dp4a on the integer pipe (into acc2) ----
                    const char* pb = sBp + (cb0 + nf * 8) * 128;
                    const int4 B0 = *(const int4*)(pb + xb0);
                    const int4 B1 = *(const int4*)(pb + 128 + xb1);
                    const int B0a[4] = {B0.x, B0.y, B0.z, B0.w};
                    const int B1a[4] = {B1.x, B1.y, B1.z, B1.w};
                    #pragma unroll
                    for (int w = 0; w < 4; w++) {
                        acc2[0][nf][0] = __dp4a(Aw[0][w], B0a[w], acc2[0][nf][0]);
                        acc2[0][nf][1] = __dp4a(Aw[0][w], B1a[w], acc2[0][nf][1]);
                        acc2[0][nf][2] = __dp4a(Aw[1][w], B0a[w], acc2[0][nf][2]);
                        acc2[0][nf][3] = __dp4a(Aw[1][w], B1a[w], acc2[0][nf][3]);
                        acc2[1][nf][0] = __dp4a(Aw[2][w], B0a[w], acc2[1][nf][0]);
                        acc2[1][nf][1] = __dp4a(Aw[2][w], B1a[w], acc2[1][nf][1]);
                        acc2[1][nf][2] = __dp4a(Aw[3][w], B0a[w], acc2[1][nf][2]);
                        acc2[1][nf][3] = __dp4a(Aw[3][w], B1a[w], acc2[1][nf][3]);
                    }
                }
            }
        }
        __syncthreads();

        if (kt + STAGES < NKT) load_stage(buf, kt + STAGES);
    }

    // epilogue: out = (acc + acc2) / (ls*rs)   (exact integer merge)
    const float al = fmaxf(__uint_as_float(g_amax_bits[0]), 1e-12f);
    const float ar = fmaxf(__uint_as_float(g_amax_bits[1]), 1e-12f);
    const float sprod = (127.0f / al) * (127.0f / ar);

    #pragma unroll
    for (int mf = 0; mf < 2; mf++) {
        #pragma unroll
        for (int nf = 0; nf < 8; nf++) {
            const int r = bm * BM + wm * 32 + mf * 16 + group;
            const int c = bn * BN + wn * 64 + nf * 8 + tig * 2;
            float2 v0, v1;
            v0.x = (float)(acc[mf][nf][0] + acc2[mf][nf][0]) / sprod;
            v0.y = (float)(acc[mf][nf][1] + acc2[mf][nf][1]) / sprod;
            v1.x = (float)(acc[mf][nf][2] + acc2[mf][nf][2]) / sprod;
            v1.y = (float)(acc[mf][nf][3] + acc2[mf][nf][3]) / sprod;
            *(float2*)(out + (size_t)r * N_DIM + c) = v0;
            *(float2*)(out + (size_t)(r + 8) * N_DIM + c) = v1;
        }
    }
}

// ---------------- launch ----------------
extern "C" void kernel_launch(void* const* d_in, const int* in_sizes, int n_in,
                              void* d_out, int out_size) {
    const float* lhs = (const float*)d_in[0];
    const float* rhs = (const float*)d_in[1];
    float* out = (float*)d_out;

    reset_kernel<<<1, 1>>>();
    amax_both_kernel<<<1024, 256>>>(lhs, rhs);
    {
        dim3 grid(N_DIM / 32, N_DIM / 32, 2);
        dim3 block(32, 8);
        quant_both_kernel<<<grid, block>>>(lhs, rhs);
    }
    {
        cudaFuncSetAttribute(gemm_s8_hybrid2,
                             cudaFuncAttributeMaxDynamicSharedMemorySize, GEMM_SMEM);
        dim3 grid(N_DIM / BN, N_DIM / BM);
        gemm_s8_hybrid2<<<grid, 256, GEMM_SMEM>>>(out);
    }
}

// round 11
// speedup vs baseline: 1.3718x; 1.3718x over previous
#include <cuda_runtime.h>
#include <cstdint>

#define N_DIM 4096
#define NELEM (N_DIM * N_DIM)

// ---------------- device scratch ----------------
__device__ unsigned g_amax_bits[2];
__device__ signed char g_qa[NELEM];          // quantized lhs, [M][K]
__device__ signed char g_qb[NELEM];          // quantized rhs^T, [N][K]

// ---------------- helpers ----------------
__device__ __forceinline__ uint32_t smem_u32(const void* p) {
    uint32_t a;
    asm("{ .reg .u64 t; cvta.to.shared.u64 t, %1; cvt.u32.u64 %0, t; }" : "=r"(a) : "l"(p));
    return a;
}
__device__ __forceinline__ void cp16s(uint32_t smem, const void* gmem) {
    asm volatile("cp.async.cg.shared.global [%0], [%1], 16;\n" :: "r"(smem), "l"(gmem));
}
__device__ __forceinline__ void cp_commit() { asm volatile("cp.async.commit_group;\n"); }
template <int N> __device__ __forceinline__ void cp_wait() {
    asm volatile("cp.async.wait_group %0;\n" :: "n"(N));
}
__device__ __forceinline__ void ldsm_x4(uint32_t& r0, uint32_t& r1, uint32_t& r2,
                                        uint32_t& r3, uint32_t addr) {
    asm volatile("ldmatrix.sync.aligned.m8n8.x4.shared.b16 {%0,%1,%2,%3}, [%4];"
                 : "=r"(r0), "=r"(r1), "=r"(r2), "=r"(r3) : "r"(addr));
}
__device__ __forceinline__ signed char quant1(float v, float s) {
    float q = rintf(v * s);
    q = fminf(fmaxf(q, -127.0f), 127.0f);
    return (signed char)(int)q;
}

// ---------------- launch #1: reset ----------------
__global__ void reset_kernel() {
    g_amax_bits[0] = 0u;
    g_amax_bits[1] = 0u;
}

// ---------------- launch #2: abs-max for BOTH tensors ----------------
__global__ void amax_both_kernel(const float* __restrict__ lhs,
                                 const float* __restrict__ rhs) {
    const int half = gridDim.x >> 1;
    const int sel = (blockIdx.x >= half) ? 1 : 0;
    const float* x = sel ? rhs : lhs;
    const int bid = sel ? (blockIdx.x - half) : blockIdx.x;

    int tid = bid * blockDim.x + threadIdx.x;
    int stride = half * blockDim.x;
    const float4* x4 = (const float4*)x;
    float m = 0.0f;
    for (int i = tid; i < NELEM / 4; i += stride) {
        float4 v = x4[i];
        m = fmaxf(m, fmaxf(fmaxf(fabsf(v.x), fabsf(v.y)),
                           fmaxf(fabsf(v.z), fabsf(v.w))));
    }
    #pragma unroll
    for (int o = 16; o; o >>= 1) m = fmaxf(m, __shfl_xor_sync(0xffffffffu, m, o));
    __shared__ float sm[32];
    int lane = threadIdx.x & 31, w = threadIdx.x >> 5;
    if (lane == 0) sm[w] = m;
    __syncthreads();
    if (w == 0) {
        m = (lane < (int)(blockDim.x >> 5)) ? sm[lane] : 0.0f;
        #pragma unroll
        for (int o = 16; o; o >>= 1) m = fmaxf(m, __shfl_xor_sync(0xffffffffu, m, o));
        if (lane == 0) atomicMax(&g_amax_bits[sel], __float_as_uint(m));
    }
}

// ---------------- launch #3: quantize lhs + quantize/transpose rhs ----------------
// grid (128, 128, 2), block (32, 8)
__global__ void quant_both_kernel(const float* __restrict__ lhs,
                                  const float* __restrict__ rhs) {
    const int tid256 = threadIdx.y * 32 + threadIdx.x;
    if (blockIdx.z == 0) {
        float amax = fmaxf(__uint_as_float(g_amax_bits[0]), 1e-12f);
        float s = 127.0f / amax;
        const int bid = blockIdx.y * gridDim.x + blockIdx.x;
        const int i = bid * 256 + tid256;
        float4 v = ((const float4*)lhs)[i];
        char4 q;
        q.x = quant1(v.x, s); q.y = quant1(v.y, s);
        q.z = quant1(v.z, s); q.w = quant1(v.w, s);
        ((char4*)g_qa)[i] = q;
    } else {
        __shared__ signed char tile[32][36];
        float amax = fmaxf(__uint_as_float(g_amax_bits[1]), 1e-12f);
        float s = 127.0f / amax;
        const int k0 = blockIdx.y * 32;
        const int n0 = blockIdx.x * 32;
        const int tx = threadIdx.x, ty = threadIdx.y;
        #pragma unroll
        for (int i = 0; i < 4; i++) {
            int k = ty + i * 8;
            float v = rhs[(size_t)(k0 + k) * N_DIM + n0 + tx];
            tile[tx][k] = quant1(v, s);
        }
        __syncthreads();
        #pragma unroll
        for (int i = 0; i < 4; i++) {
            int n = ty + i * 8;
            g_qb[(size_t)(n0 + n) * N_DIM + k0 + tx] = tile[n][tx];
        }
    }
}

// ---------------- launch #4: warp-specialized hybrid s8 GEMM ----------------
// 128x128x128 tile, 3-stage cp.async, 2 CTAs/SM.
// Warps 0-3: tensor mma for rows [0,64), full K.     (warp tile 32x64)
// Warps 4-7: __dp4a for rows [64,128), full K.       (warp tile 32x64)
// Both pipes run concurrently with homogeneous per-warp instruction streams.
#define BM 128
#define BN 128
#define BKB 128
#define STAGES 3
#define NKT (N_DIM / BKB)                     // 32
#define A_STAGE_BYTES (BM * BKB)              // 16384
#define B_STAGE_BYTES (BN * BKB)              // 16384
#define STAGE_BYTES (A_STAGE_BYTES + B_STAGE_BYTES)   // 32768
#define GEMM_SMEM (STAGES * STAGE_BYTES)      // 98304

__global__ __launch_bounds__(256, 2) void gemm_s8_wspec(float* __restrict__ out) {
    extern __shared__ __align__(1024) char smem[];
    const uint32_t smem_base = smem_u32(smem);
    const int tid = threadIdx.x;
    const int wid = tid >> 5, lane = tid & 31;
    const int bm = blockIdx.y, bn = blockIdx.x;

    int acc[2][8][4];
    #pragma unroll
    for (int a = 0; a < 2; a++)
        #pragma unroll
        for (int b = 0; b < 8; b++)
            #pragma unroll
            for (int c = 0; c < 4; c++) acc[a][b][c] = 0;

    const signed char* gA = g_qa + (size_t)(bm * BM) * N_DIM;
    const signed char* gB = g_qb + (size_t)(bn * BN) * N_DIM;

    auto load_stage = [&](int s, int kt) {
        const uint32_t sa = smem_base + s * STAGE_BYTES;
        const uint32_t sb = sa + A_STAGE_BYTES;
        #pragma unroll
        for (int i = 0; i < 4; i++) {
            const int ci = tid + i * 256;
            const int row = ci >> 3, c = ci & 7;
            cp16s(sa + row * 128 + ((c ^ (row & 7)) << 4),
                  gA + (size_t)row * N_DIM + kt * BKB + c * 16);
        }
        #pragma unroll
        for (int i = 0; i < 4; i++) {
            const int ci = tid + i * 256;
            const int row = ci >> 3, c = ci & 7;
            cp16s(sb + row * 128 + ((c ^ (row & 7)) << 4),
                  gB + (size_t)row * N_DIM + kt * BKB + c * 16);
        }
        cp_commit();
    };

    #pragma unroll
    for (int s = 0; s < STAGES; s++) load_stage(s, s);

    const int lrow16 = lane & 15;
    const int half = (lane >> 4) & 1;
    const int swz = lane & 7;
    const int group = lane >> 2, tig = lane & 3;

    // warp role / sub-tile assignment
    const bool is_tensor = (wid < 4);
    const int w2 = is_tensor ? wid : (wid - 4);
    const int rowb = (is_tensor ? 0 : 64) + (w2 & 1) * 32;   // CTA-relative row base
    const int colb = (w2 >> 1) * 64;                          // CTA-relative col base

    for (int kt = 0; kt < NKT; kt++) {
        const int buf = kt % STAGES;
        {
            const int rem = NKT - kt;
            if (rem > 2) cp_wait<2>();
            else if (rem == 2) cp_wait<1>();
            else cp_wait<0>();
        }
        __syncthreads();

        const uint32_t sa = smem_base + buf * STAGE_BYTES;
        const uint32_t sb = sa + A_STAGE_BYTES;

        if (is_tensor) {
            // ===== tensor warps: full K=128 via mma.m16n8k32 =====
            const uint32_t aRowBase = sa + (rowb + lrow16) * 128;
            const uint32_t bRowBase = sb + (colb + lrow16) * 128;
            #pragma unroll
            for (int ks = 0; ks < 4; ks++) {
                const uint32_t cs = (uint32_t)(((ks * 2 + half) ^ swz) << 4);
                uint32_t af[2][4];
                #pragma unroll
                for (int mf = 0; mf < 2; mf++)
                    ldsm_x4(af[mf][0], af[mf][1], af[mf][2], af[mf][3],
                            aRowBase + mf * 16 * 128 + cs);
                uint32_t bf[8][2];
                #pragma unroll
                for (int np = 0; np < 4; np++) {
                    uint32_t m0, m1, m2, m3;
                    ldsm_x4(m0, m1, m2, m3, bRowBase + np * 16 * 128 + cs);
                    bf[2 * np][0] = m0; bf[2 * np + 1][0] = m1;
                    bf[2 * np][1] = m2; bf[2 * np + 1][1] = m3;
                }
                #pragma unroll
                for (int mf = 0; mf < 2; mf++) {
                    #pragma unroll
                    for (int nf = 0; nf < 8; nf++) {
                        asm volatile(
                            "mma.sync.aligned.m16n8k32.row.col.s32.s8.s8.s32 "
                            "{%0,%1,%2,%3}, {%4,%5,%6,%7}, {%8,%9}, {%0,%1,%2,%3};\n"
                            : "+r"(acc[mf][nf][0]), "+r"(acc[mf][nf][1]),
                              "+r"(acc[mf][nf][2]), "+r"(acc[mf][nf][3])
                            : "r"(af[mf][0]), "r"(af[mf][1]), "r"(af[mf][2]), "r"(af[mf][3]),
                              "r"(bf[nf][0]), "r"(bf[nf][1]));
                    }
                }
            }
        } else {
            // ===== dp4a warps: full K=128 via __dp4a =====
            const char* sAp = smem + buf * STAGE_BYTES;
            const char* sBp = sAp + A_STAGE_BYTES;
            const int r0 = rowb + group;
            const int cb0 = colb + tig * 2;
            const int xb0s = tig * 2, xb1s = tig * 2 + 1;
            #pragma unroll
            for (int c = 0; c < 8; c++) {
                const int xa = (c ^ group) << 4;
                const int4 A0 = *(const int4*)(sAp + (r0     ) * 128 + xa);
                const int4 A1 = *(const int4*)(sAp + (r0 +  8) * 128 + xa);
                const int4 A2 = *(const int4*)(sAp + (r0 + 16) * 128 + xa);
                const int4 A3 = *(const int4*)(sAp + (r0 + 24) * 128 + xa);
                const int Aw[4][4] = {{A0.x, A0.y, A0.z, A0.w},
                                      {A1.x, A1.y, A1.z, A1.w},
                                      {A2.x, A2.y, A2.z, A2.w},
                                      {A3.x, A3.y, A3.z, A3.w}};
                const int xb0 = (c ^ xb0s) << 4;
                const int xb1 = (c ^ xb1s) << 4;
                #pragma unroll
                for (int nf = 0; nf < 8; nf++) {
                    const char* pb = sBp + (cb0 + nf * 8) * 128;
                    const int4 B0 = *(const int4*)(pb + xb0);
                    const int4 B1 = *(const int4*)(pb + 128 + xb1);
                    const int B0a[4] = {B0.x, B0.y, B0.z, B0.w};
                    const int B1a[4] = {B1.x, B1.y, B1.z, B1.w};
                    #pragma unroll
                    for (int w = 0; w < 4; w++) {
                        acc[0][nf][0] = __dp4a(Aw[0][w], B0a[w], acc[0][nf][0]);
                        acc[0][nf][1] = __dp4a(Aw[0][w], B1a[w], acc[0][nf][1]);
                        acc[0][nf][2] = __dp4a(Aw[1][w], B0a[w], acc[0][nf][2]);
                        acc[0][nf][3] = __dp4a(Aw[1][w], B1a[w], acc[0][nf][3]);
                        acc[1][nf][0] = __dp4a(Aw[2][w], B0a[w], acc[1][nf][0]);
                        acc[1][nf][1] = __dp4a(Aw[2][w], B1a[w], acc[1][nf][1]);
                        acc[1][nf][2] = __dp4a(Aw[3][w], B0a[w], acc[1][nf][2]);
                        acc[1][nf][3] = __dp4a(Aw[3][w], B1a[w], acc[1][nf][3]);
                    }
                }
            }
        }
        __syncthreads();

        if (kt + STAGES < NKT) load_stage(buf, kt + STAGES);
    }

    // epilogue: out = acc / (ls*rs)   (both roles share the same thread layout)
    const float al = fmaxf(__uint_as_float(g_amax_bits[0]), 1e-12f);
    const float ar = fmaxf(__uint_as_float(g_amax_bits[1]), 1e-12f);
    const float sprod = (127.0f / al) * (127.0f / ar);

    #pragma unroll
    for (int mf = 0; mf < 2; mf++) {
        #pragma unroll
        for (int nf = 0; nf < 8; nf++) {
            const int r = bm * BM + rowb + mf * 16 + group;
            const int c = bn * BN + colb + nf * 8 + tig * 2;
            float2 v0, v1;
            v0.x = (float)acc[mf][nf][0] / sprod;
            v0.y = (float)acc[mf][nf][1] / sprod;
            v1.x = (float)acc[mf][nf][2] / sprod;
            v1.y = (float)acc[mf][nf][3] / sprod;
            *(float2*)(out + (size_t)r * N_DIM + c) = v0;
            *(float2*)(out + (size_t)(r + 8) * N_DIM + c) = v1;
        }
    }
}

// ---------------- launch ----------------
extern "C" void kernel_launch(void* const* d_in, const int* in_sizes, int n_in,
                              void* d_out, int out_size) {
    const float* lhs = (const float*)d_in[0];
    const float* rhs = (const float*)d_in[1];
    float* out = (float*)d_out;

    reset_kernel<<<1, 1>>>();
    amax_both_kernel<<<1024, 256>>>(lhs, rhs);
    {
        dim3 grid(N_DIM / 32, N_DIM / 32, 2);
        dim3 block(32, 8);
        quant_both_kernel<<<grid, block>>>(lhs, rhs);
    }
    {
        cudaFuncSetAttribute(gemm_s8_wspec,
                             cudaFuncAttributeMaxDynamicSharedMemorySize, GEMM_SMEM);
        dim3 grid(N_DIM / BN, N_DIM / BM);
        gemm_s8_wspec<<<grid, 256, GEMM_SMEM>>>(out);
    }
}